// round 13
// baseline (speedup 1.0000x reference)
#include <cuda_runtime.h>
#include <cuda_bf16.h>
#include <math.h>

// Problem dims
#define BATCH 64
#define SEQ   512
#define HID   768
#define ATTH  100
#define CLSH  300

#define NTOK (BATCH*SEQ)          // 32768
#define HS_ELEMS (BATCH*SEQ*HID)  // 25165824

// Output layout
#define OUT_HID_OFF  5
#define OUT_MASK_OFF (5 + HS_ELEMS)
#define OUT_SENT_OFF (5 + HS_ELEMS + NTOK)

#define PSPLIT 8

// ---------------- device scratch ----------------
__device__ float g_token_att[NTOK];
__device__ float g_pool_part[PSPLIT * BATCH * HID];
__device__ float g_sent_j[BATCH * 8 * CLSH];
__device__ float g_sum[BATCH];
__device__ float g_maxm[BATCH];
__device__ float g_minm[BATCH];
__device__ float g_slab[BATCH];
__device__ float g_tl[BATCH];
__device__ float g_sent[BATCH];

__device__ __forceinline__ void mma_tf32(float& d0, float& d1, float& d2, float& d3,
                                         unsigned a0, unsigned a1, unsigned a2, unsigned a3,
                                         unsigned b0, unsigned b1) {
    asm volatile(
        "mma.sync.aligned.m16n8k8.row.col.f32.tf32.tf32.f32 "
        "{%0,%1,%2,%3}, {%4,%5,%6,%7}, {%8,%9}, {%0,%1,%2,%3};"
        : "+f"(d0), "+f"(d1), "+f"(d2), "+f"(d3)
        : "r"(a0), "r"(a1), "r"(a2), "r"(a3), "r"(b0), "r"(b1));
}

__device__ __forceinline__ void cp16(float* smem_dst, const float* gsrc) {
    unsigned s = (unsigned)__cvta_generic_to_shared(smem_dst);
    asm volatile("cp.async.cg.shared.global [%0], [%1], 16;" :: "r"(s), "l"(gsrc));
}
__device__ __forceinline__ void cp_commit() {
    asm volatile("cp.async.commit_group;");
}
__device__ __forceinline__ void cp_wait1() {
    asm volatile("cp.async.wait_group 1;");
}
// named barrier for the 8 MMA warps only (echo warps never touch it)
__device__ __forceinline__ void bar_mma() {
    asm volatile("bar.sync 1, 256;" ::: "memory");
}

// =====================================================================
// Kernel 1: warp-specialized token-attention head.
// 512 threads: warps 0-7 = tf32 MMA pipeline (R7-identical, M=32/warp),
//              warps 8-15 = hidden_states echo (LDG.128 -> scalar STG).
// =====================================================================
#define MT     256
#define KT     32
#define NT     13
#define KCH    (HID / KT)      // 24
#define ASTR   36
#define WSTR   104
#define STAGES 3
#define A_TILE_FL (MT * ASTR)  // 9216
#define W_TILE_FL (KT * WSTR)  // 3328
#define ATT_SMEM_BYTES (STAGES * (A_TILE_FL + W_TILE_FL) * 4)   // 150528

__global__ void __launch_bounds__(512)
att_gemm_kernel(const float* __restrict__ A,
                const float* __restrict__ W1,
                const float* __restrict__ b1,
                const float* __restrict__ W2,
                const float* __restrict__ b2,
                float* __restrict__ tok,
                float* __restrict__ out_hidden)
{
    extern __shared__ float sm[];
    float* Abuf = sm;
    float* Wbuf = sm + STAGES * A_TILE_FL;

    const int tid  = threadIdx.x;
    const int m0   = blockIdx.x * MT;

    if (tid >= 256) {
        // ---------------- echo warps ----------------
        const int et = tid - 256;                      // 0..255
        const float4* src = reinterpret_cast<const float4*>(A + (size_t)m0 * HID);
        float* dst = out_hidden + (size_t)m0 * HID;
        // 256 rows x 768 floats = 49152 float4; 192 per thread, coalesced
#pragma unroll 4
        for (int i = 0; i < 192; i++) {
            int f = i * 256 + et;
            float4 v = src[f];
            float* o = dst + (size_t)f * 4;            // 4B-aligned dest
            o[0] = v.x; o[1] = v.y; o[2] = v.z; o[3] = v.w;
        }
        return;
    }

    // ---------------- MMA warps (R7-identical, named barrier) ----------------
    const int lane = tid & 31;
    const int wid  = tid >> 5;          // 0..7
    const int q    = lane >> 2;
    const int r4   = lane & 3;
    const int wr   = wid * 32;

    for (int i = tid; i < STAGES * KT * 4; i += 256) {
        int st = i / (KT * 4);
        int r  = (i >> 2) % KT;
        int c  = i & 3;
        Wbuf[st * W_TILE_FL + r * WSTR + ATTH + c] = 0.f;
    }

    float acc0[NT][4], acc1[NT][4];
#pragma unroll
    for (int nt = 0; nt < NT; nt++)
#pragma unroll
        for (int c = 0; c < 4; c++) { acc0[nt][c] = 0.f; acc1[nt][c] = 0.f; }

    auto issue = [&](int st, int k0) {
        float* As = Abuf + st * A_TILE_FL;
        float* Ws = Wbuf + st * W_TILE_FL;
#pragma unroll
        for (int i = 0; i < 8; i++) {
            int f   = i * 256 + tid;
            int row = f >> 3;
            int c16 = f & 7;
            cp16(As + row * ASTR + c16 * 4,
                 A + (size_t)(m0 + row) * HID + k0 + c16 * 4);
        }
#pragma unroll
        for (int i = 0; i < 4; i++) {
            int e = i * 256 + tid;
            if (e < KT * 25) {
                int kr = e / 25;
                int cc = e % 25;
                cp16(Ws + kr * WSTR + cc * 4,
                     W1 + (size_t)(k0 + kr) * ATTH + cc * 4);
            }
        }
    };

    issue(0, 0);       cp_commit();
    issue(1, KT);      cp_commit();

    for (int kc = 0; kc < KCH; kc++) {
        cp_wait1();
        bar_mma();
        if (kc + 2 < KCH) issue((kc + 2) % STAGES, (kc + 2) * KT);
        cp_commit();

        const float* As = Abuf + (kc % STAGES) * A_TILE_FL;
        const float* Ws = Wbuf + (kc % STAGES) * W_TILE_FL;

#pragma unroll
        for (int ks = 0; ks < 4; ks++) {
            const int k = ks * 8;
            unsigned a00 = __float_as_uint(As[(wr + q     ) * ASTR + k + r4]);
            unsigned a01 = __float_as_uint(As[(wr + q + 8 ) * ASTR + k + r4]);
            unsigned a02 = __float_as_uint(As[(wr + q     ) * ASTR + k + r4 + 4]);
            unsigned a03 = __float_as_uint(As[(wr + q + 8 ) * ASTR + k + r4 + 4]);
            unsigned a10 = __float_as_uint(As[(wr + q + 16) * ASTR + k + r4]);
            unsigned a11 = __float_as_uint(As[(wr + q + 24) * ASTR + k + r4]);
            unsigned a12 = __float_as_uint(As[(wr + q + 16) * ASTR + k + r4 + 4]);
            unsigned a13 = __float_as_uint(As[(wr + q + 24) * ASTR + k + r4 + 4]);
#pragma unroll
            for (int nt = 0; nt < NT; nt++) {
                unsigned b0 = __float_as_uint(Ws[(k + r4    ) * WSTR + nt * 8 + q]);
                unsigned b1 = __float_as_uint(Ws[(k + r4 + 4) * WSTR + nt * 8 + q]);
                mma_tf32(acc0[nt][0], acc0[nt][1], acc0[nt][2], acc0[nt][3],
                         a00, a01, a02, a03, b0, b1);
                mma_tf32(acc1[nt][0], acc1[nt][1], acc1[nt][2], acc1[nt][3],
                         a10, a11, a12, a13, b0, b1);
            }
        }
    }

    const float bias2 = b2[0];
    float p0 = 0.f, p1 = 0.f, p2 = 0.f, p3 = 0.f;
#pragma unroll
    for (int nt = 0; nt < NT; nt++) {
        int j0 = nt * 8 + 2 * r4;
        int j1 = j0 + 1;
        float bb0 = 0.f, bb1 = 0.f, ww0 = 0.f, ww1 = 0.f;
        if (j0 < ATTH) { bb0 = b1[j0]; ww0 = W2[j0]; }
        if (j1 < ATTH) { bb1 = b1[j1]; ww1 = W2[j1]; }
        p0 += tanhf(acc0[nt][0] + bb0) * ww0 + tanhf(acc0[nt][1] + bb1) * ww1;
        p1 += tanhf(acc0[nt][2] + bb0) * ww0 + tanhf(acc0[nt][3] + bb1) * ww1;
        p2 += tanhf(acc1[nt][0] + bb0) * ww0 + tanhf(acc1[nt][1] + bb1) * ww1;
        p3 += tanhf(acc1[nt][2] + bb0) * ww0 + tanhf(acc1[nt][3] + bb1) * ww1;
    }
#pragma unroll
    for (int o = 1; o <= 2; o <<= 1) {
        p0 += __shfl_xor_sync(0xffffffffu, p0, o);
        p1 += __shfl_xor_sync(0xffffffffu, p1, o);
        p2 += __shfl_xor_sync(0xffffffffu, p2, o);
        p3 += __shfl_xor_sync(0xffffffffu, p3, o);
    }
    if (r4 == 0) {
        int m = m0 + wr + q;
        tok[m]      = 1.f / (1.f + expf(-(p0 + bias2)));
        tok[m + 8]  = 1.f / (1.f + expf(-(p1 + bias2)));
        tok[m + 16] = 1.f / (1.f + expf(-(p2 + bias2)));
        tok[m + 24] = 1.f / (1.f + expf(-(p3 + bias2)));
    }
}

// =====================================================================
// Kernel 2: segment-max + mask + per-row stats (warp-shuffle reductions).
// =====================================================================
__global__ void __launch_bounds__(512)
seg_mask_kernel(const int* __restrict__ off,
                const float* __restrict__ labels,
                const float* __restrict__ tok,
                float* __restrict__ out_masked)
{
    const int b = blockIdx.x;
    const int s = threadIdx.x;
    const int lane = s & 31;
    const int warp = s >> 5;
    const int base = b * SEQ;

    float lab  = labels[base + s];
    bool  cont = (off[(size_t)(base + s) * 2] != 0);

    float masked = 0.f;
    if (!cont) {
        float wa = tok[base + s];
        int t = s + 1;
        while (t < SEQ && off[(size_t)(base + t) * 2] != 0) {
            wa = fmaxf(wa, tok[base + t]);
            t++;
        }
        if (lab != -1.0f) masked = wa;
    }
    out_masked[base + s] = masked;

    float z = (lab == 1.0f) ? 1.0f : 0.0f;
    float v_sum = masked;
    float v_max = masked;
    float v_min = (masked == 0.f) ? 1.f : masked;
    float v_lab = lab;
    float v_tl  = (masked - z) * (masked - z);

#pragma unroll
    for (int o = 16; o > 0; o >>= 1) {
        v_sum += __shfl_xor_sync(0xffffffffu, v_sum, o);
        v_max = fmaxf(v_max, __shfl_xor_sync(0xffffffffu, v_max, o));
        v_min = fminf(v_min, __shfl_xor_sync(0xffffffffu, v_min, o));
        v_lab = fmaxf(v_lab, __shfl_xor_sync(0xffffffffu, v_lab, o));
        v_tl  += __shfl_xor_sync(0xffffffffu, v_tl, o);
    }

    __shared__ float ws[16][5];
    if (lane == 0) {
        ws[warp][0] = v_sum; ws[warp][1] = v_max; ws[warp][2] = v_min;
        ws[warp][3] = v_lab; ws[warp][4] = v_tl;
    }
    __syncthreads();

    if (warp == 0) {
        float a0 = (lane < 16) ? ws[lane][0] : 0.f;
        float a1 = (lane < 16) ? ws[lane][1] : -1e30f;
        float a2 = (lane < 16) ? ws[lane][2] :  1e30f;
        float a3 = (lane < 16) ? ws[lane][3] : -1e30f;
        float a4 = (lane < 16) ? ws[lane][4] : 0.f;
#pragma unroll
        for (int o = 8; o > 0; o >>= 1) {
            a0 += __shfl_xor_sync(0xffffffffu, a0, o);
            a1 = fmaxf(a1, __shfl_xor_sync(0xffffffffu, a1, o));
            a2 = fminf(a2, __shfl_xor_sync(0xffffffffu, a2, o));
            a3 = fmaxf(a3, __shfl_xor_sync(0xffffffffu, a3, o));
            a4 += __shfl_xor_sync(0xffffffffu, a4, o);
        }
        if (lane == 0) {
            g_sum[b] = a0; g_maxm[b] = a1; g_minm[b] = a2;
            g_slab[b] = a3; g_tl[b] = a4;
        }
    }
}

// =====================================================================
// Kernel 3: pooling partials (read-only). grid (BATCH, PSPLIT), 192 thr.
// =====================================================================
__global__ void __launch_bounds__(192)
pool_kernel(const float* __restrict__ hs,
            const float* __restrict__ masked)
{
    const int b  = blockIdx.x;
    const int ss = blockIdx.y;
    const int tid = threadIdx.x;
    const int SCH = SEQ / PSPLIT;              // 64
    const int s0 = ss * SCH;

    __shared__ float nm[SCH];
    if (tid < SCH) nm[tid] = masked[b * SEQ + s0 + tid];
    __syncthreads();

    const size_t rowbase = (size_t)b * SEQ * HID + (size_t)s0 * HID;
    const float4* hp = reinterpret_cast<const float4*>(hs + rowbase) + tid;

    float4 acc = make_float4(0.f, 0.f, 0.f, 0.f);
#pragma unroll 8
    for (int s = 0; s < SCH; s++) {
        float4 v = hp[(size_t)s * (HID / 4)];
        float w = nm[s];
        acc.x += v.x * w; acc.y += v.y * w;
        acc.z += v.z * w; acc.w += v.w * w;
    }

    float4* dst = reinterpret_cast<float4*>(
        g_pool_part + ((size_t)ss * BATCH + b) * HID) + tid;
    *dst = acc;
}

// =====================================================================
// Kernel 4: sentence head split-k partials. grid (BATCH, 8), 320 threads.
// =====================================================================
__global__ void __launch_bounds__(320)
sent_part_kernel(const float* __restrict__ W3)
{
    const int b  = blockIdx.x;
    const int ks = blockIdx.y;
    const int tid = threadIdx.x;
    const int k0 = ks * 96;

    __shared__ float pl[96];
    if (tid < 96) {
        const int h = k0 + tid;
        float v = 0.f;
#pragma unroll
        for (int ss = 0; ss < PSPLIT; ss++)
            v += g_pool_part[((size_t)ss * BATCH + b) * HID + h];
        pl[tid] = v / g_sum[b];
    }
    __syncthreads();

    if (tid < CLSH) {
        const float* wp = W3 + (size_t)k0 * CLSH + tid;
        float a0 = 0.f, a1 = 0.f, a2 = 0.f, a3 = 0.f;
#pragma unroll 6
        for (int k = 0; k < 96; k += 4) {
            a0 += pl[k]     * __ldg(&wp[(size_t)k * CLSH]);
            a1 += pl[k + 1] * __ldg(&wp[(size_t)(k + 1) * CLSH]);
            a2 += pl[k + 2] * __ldg(&wp[(size_t)(k + 2) * CLSH]);
            a3 += pl[k + 3] * __ldg(&wp[(size_t)(k + 3) * CLSH]);
        }
        g_sent_j[((size_t)b * 8 + ks) * CLSH + tid] = (a0 + a1) + (a2 + a3);
    }
}

// =====================================================================
// Kernel 5: sentence combine. grid (BATCH), 320 threads.
// =====================================================================
__global__ void __launch_bounds__(320)
sent_comb_kernel(const float* __restrict__ b3,
                 const float* __restrict__ W4,
                 const float* __restrict__ b4,
                 float* __restrict__ out_sent)
{
    const int b = blockIdx.x;
    const int tid = threadIdx.x;

    float v = 0.f;
    if (tid < CLSH) {
        float s = b3[tid];
#pragma unroll
        for (int ks = 0; ks < 8; ks++)
            s += g_sent_j[((size_t)b * 8 + ks) * CLSH + tid];
        v = tanhf(s) * W4[tid];
    }

    __shared__ float red[512];
    red[tid] = v;
    if (tid + 320 < 512) red[tid + 320] = 0.f;
    __syncthreads();
    for (int st = 256; st > 0; st >>= 1) {
        if (tid < st) red[tid] += red[tid + st];
        __syncthreads();
    }
    if (tid == 0) {
        float sv = 1.f / (1.f + expf(-(red[0] + b4[0])));
        g_sent[b] = sv;
        out_sent[b] = sv;
    }
}

// =====================================================================
// Kernel 6: finalize losses.
// =====================================================================
__global__ void __launch_bounds__(64)
final_kernel(float* __restrict__ out)
{
    const int b = threadIdx.x;
    float sl = g_sent[b] - g_slab[b]; sl *= sl;
    float ra = g_minm[b] * g_minm[b];
    float d  = g_maxm[b] - g_slab[b]; float rb = d * d;
    float tl = g_tl[b];

    __shared__ float s1[64], s2[64], s3[64], s4[64];
    s1[b] = sl; s2[b] = tl; s3[b] = ra; s4[b] = rb;
    __syncthreads();
    for (int st = 32; st > 0; st >>= 1) {
        if (b < st) { s1[b] += s1[b+st]; s2[b] += s2[b+st]; s3[b] += s3[b+st]; s4[b] += s4[b+st]; }
        __syncthreads();
    }
    if (b == 0) {
        float sentence = s1[0], token = s2[0], rega = s3[0], regb = s4[0];
        out[0] = sentence + token + 0.01f * (rega + regb);
        out[1] = sentence;
        out[2] = token;
        out[3] = rega;
        out[4] = regb;
    }
}

// =====================================================================
extern "C" void kernel_launch(void* const* d_in, const int* in_sizes, int n_in,
                              void* d_out, int out_size)
{
    const float* hs     = (const float*)d_in[0];
    const int*   off    = (const int*)  d_in[1];
    const float* labels = (const float*)d_in[2];
    const float* W1     = (const float*)d_in[3];
    const float* b1     = (const float*)d_in[4];
    const float* W2     = (const float*)d_in[5];
    const float* b2     = (const float*)d_in[6];
    const float* W3     = (const float*)d_in[7];
    const float* b3     = (const float*)d_in[8];
    const float* W4     = (const float*)d_in[9];
    const float* b4     = (const float*)d_in[10];

    float* out = (float*)d_out;
    float* out_hidden = out + OUT_HID_OFF;
    float* out_masked = out + OUT_MASK_OFF;
    float* out_sent   = out + OUT_SENT_OFF;

    float* tok; cudaGetSymbolAddress((void**)&tok, g_token_att);

    cudaFuncSetAttribute(att_gemm_kernel,
                         cudaFuncAttributeMaxDynamicSharedMemorySize,
                         ATT_SMEM_BYTES);

    // Stage A: warp-specialized att (8 MMA warps + 8 echo warps)
    att_gemm_kernel<<<NTOK / MT, 512, ATT_SMEM_BYTES>>>(hs, W1, b1, W2, b2,
                                                        tok, out_hidden);

    // Stage B: segment max, mask, row stats
    seg_mask_kernel<<<BATCH, SEQ>>>(off, labels, tok, out_masked);

    // Stage C: pooling partials (read-only)
    dim3 pg(BATCH, PSPLIT);
    pool_kernel<<<pg, 192>>>(hs, out_masked);

    // Stage D: sentence head partials (k-split)
    dim3 sg(BATCH, 8);
    sent_part_kernel<<<sg, 320>>>(W3);

    // Stage E: sentence combine
    sent_comb_kernel<<<BATCH, 320>>>(b3, W4, b4, out_sent);

    // Stage F: losses
    final_kernel<<<1, 64>>>(out);
}

// round 14
// speedup vs baseline: 1.2451x; 1.2451x over previous
#include <cuda_runtime.h>
#include <cuda_bf16.h>
#include <math.h>

// Problem dims
#define BATCH 64
#define SEQ   512
#define HID   768
#define ATTH  100
#define CLSH  300

#define NTOK (BATCH*SEQ)          // 32768
#define HS_ELEMS (BATCH*SEQ*HID)  // 25165824

// Output layout
#define OUT_HID_OFF  5
#define OUT_MASK_OFF (5 + HS_ELEMS)
#define OUT_SENT_OFF (5 + HS_ELEMS + NTOK)

#define PSPLIT 8
#define BG     8      // batches per sent_part block

// ---------------- device scratch ----------------
__device__ float g_token_att[NTOK];
__device__ float g_pool_part[PSPLIT * BATCH * HID];
__device__ float g_sent_j[BATCH * 8 * CLSH];
__device__ float g_sum[BATCH];
__device__ float g_maxm[BATCH];
__device__ float g_minm[BATCH];
__device__ float g_slab[BATCH];
__device__ float g_tl[BATCH];
__device__ float g_sent[BATCH];

__device__ __forceinline__ void mma_tf32(float& d0, float& d1, float& d2, float& d3,
                                         unsigned a0, unsigned a1, unsigned a2, unsigned a3,
                                         unsigned b0, unsigned b1) {
    asm volatile(
        "mma.sync.aligned.m16n8k8.row.col.f32.tf32.tf32.f32 "
        "{%0,%1,%2,%3}, {%4,%5,%6,%7}, {%8,%9}, {%0,%1,%2,%3};"
        : "+f"(d0), "+f"(d1), "+f"(d2), "+f"(d3)
        : "r"(a0), "r"(a1), "r"(a2), "r"(a3), "r"(b0), "r"(b1));
}

__device__ __forceinline__ void cp16(float* smem_dst, const float* gsrc) {
    unsigned s = (unsigned)__cvta_generic_to_shared(smem_dst);
    asm volatile("cp.async.cg.shared.global [%0], [%1], 16;" :: "r"(s), "l"(gsrc));
}
__device__ __forceinline__ void cp_commit() {
    asm volatile("cp.async.commit_group;");
}
__device__ __forceinline__ void cp_wait1() {
    asm volatile("cp.async.wait_group 1;");
}

// =====================================================================
// Kernel 1: token-attention head (R7-exact). tf32 MMA, cp.async pipeline.
// MT=256 rows/block, 256 threads, warp owns M=32 (two m16 tiles).
// =====================================================================
#define MT     256
#define KT     32
#define NT     13
#define KCH    (HID / KT)      // 24
#define ASTR   36
#define WSTR   104
#define STAGES 3
#define A_TILE_FL (MT * ASTR)  // 9216
#define W_TILE_FL (KT * WSTR)  // 3328
#define ATT_SMEM_BYTES (STAGES * (A_TILE_FL + W_TILE_FL) * 4)   // 150528

__global__ void __launch_bounds__(256)
att_gemm_kernel(const float* __restrict__ A,
                const float* __restrict__ W1,
                const float* __restrict__ b1,
                const float* __restrict__ W2,
                const float* __restrict__ b2,
                float* __restrict__ tok)
{
    extern __shared__ float sm[];
    float* Abuf = sm;
    float* Wbuf = sm + STAGES * A_TILE_FL;

    const int tid  = threadIdx.x;
    const int lane = tid & 31;
    const int wid  = tid >> 5;
    const int q    = lane >> 2;
    const int r4   = lane & 3;
    const int m0   = blockIdx.x * MT;
    const int wr   = wid * 32;

    for (int i = tid; i < STAGES * KT * 4; i += 256) {
        int st = i / (KT * 4);
        int r  = (i >> 2) % KT;
        int c  = i & 3;
        Wbuf[st * W_TILE_FL + r * WSTR + ATTH + c] = 0.f;
    }

    float acc0[NT][4], acc1[NT][4];
#pragma unroll
    for (int nt = 0; nt < NT; nt++)
#pragma unroll
        for (int c = 0; c < 4; c++) { acc0[nt][c] = 0.f; acc1[nt][c] = 0.f; }

    auto issue = [&](int st, int k0) {
        float* As = Abuf + st * A_TILE_FL;
        float* Ws = Wbuf + st * W_TILE_FL;
#pragma unroll
        for (int i = 0; i < 8; i++) {
            int f   = i * 256 + tid;
            int row = f >> 3;
            int c16 = f & 7;
            cp16(As + row * ASTR + c16 * 4,
                 A + (size_t)(m0 + row) * HID + k0 + c16 * 4);
        }
#pragma unroll
        for (int i = 0; i < 4; i++) {
            int e = i * 256 + tid;
            if (e < KT * 25) {
                int kr = e / 25;
                int cc = e % 25;
                cp16(Ws + kr * WSTR + cc * 4,
                     W1 + (size_t)(k0 + kr) * ATTH + cc * 4);
            }
        }
    };

    issue(0, 0);       cp_commit();
    issue(1, KT);      cp_commit();

    for (int kc = 0; kc < KCH; kc++) {
        cp_wait1();
        __syncthreads();
        if (kc + 2 < KCH) issue((kc + 2) % STAGES, (kc + 2) * KT);
        cp_commit();

        const float* As = Abuf + (kc % STAGES) * A_TILE_FL;
        const float* Ws = Wbuf + (kc % STAGES) * W_TILE_FL;

#pragma unroll
        for (int ks = 0; ks < 4; ks++) {
            const int k = ks * 8;
            unsigned a00 = __float_as_uint(As[(wr + q     ) * ASTR + k + r4]);
            unsigned a01 = __float_as_uint(As[(wr + q + 8 ) * ASTR + k + r4]);
            unsigned a02 = __float_as_uint(As[(wr + q     ) * ASTR + k + r4 + 4]);
            unsigned a03 = __float_as_uint(As[(wr + q + 8 ) * ASTR + k + r4 + 4]);
            unsigned a10 = __float_as_uint(As[(wr + q + 16) * ASTR + k + r4]);
            unsigned a11 = __float_as_uint(As[(wr + q + 24) * ASTR + k + r4]);
            unsigned a12 = __float_as_uint(As[(wr + q + 16) * ASTR + k + r4 + 4]);
            unsigned a13 = __float_as_uint(As[(wr + q + 24) * ASTR + k + r4 + 4]);
#pragma unroll
            for (int nt = 0; nt < NT; nt++) {
                unsigned b0 = __float_as_uint(Ws[(k + r4    ) * WSTR + nt * 8 + q]);
                unsigned b1 = __float_as_uint(Ws[(k + r4 + 4) * WSTR + nt * 8 + q]);
                mma_tf32(acc0[nt][0], acc0[nt][1], acc0[nt][2], acc0[nt][3],
                         a00, a01, a02, a03, b0, b1);
                mma_tf32(acc1[nt][0], acc1[nt][1], acc1[nt][2], acc1[nt][3],
                         a10, a11, a12, a13, b0, b1);
            }
        }
    }

    const float bias2 = b2[0];
    float p0 = 0.f, p1 = 0.f, p2 = 0.f, p3 = 0.f;
#pragma unroll
    for (int nt = 0; nt < NT; nt++) {
        int j0 = nt * 8 + 2 * r4;
        int j1 = j0 + 1;
        float bb0 = 0.f, bb1 = 0.f, ww0 = 0.f, ww1 = 0.f;
        if (j0 < ATTH) { bb0 = b1[j0]; ww0 = W2[j0]; }
        if (j1 < ATTH) { bb1 = b1[j1]; ww1 = W2[j1]; }
        p0 += tanhf(acc0[nt][0] + bb0) * ww0 + tanhf(acc0[nt][1] + bb1) * ww1;
        p1 += tanhf(acc0[nt][2] + bb0) * ww0 + tanhf(acc0[nt][3] + bb1) * ww1;
        p2 += tanhf(acc1[nt][0] + bb0) * ww0 + tanhf(acc1[nt][1] + bb1) * ww1;
        p3 += tanhf(acc1[nt][2] + bb0) * ww0 + tanhf(acc1[nt][3] + bb1) * ww1;
    }
#pragma unroll
    for (int o = 1; o <= 2; o <<= 1) {
        p0 += __shfl_xor_sync(0xffffffffu, p0, o);
        p1 += __shfl_xor_sync(0xffffffffu, p1, o);
        p2 += __shfl_xor_sync(0xffffffffu, p2, o);
        p3 += __shfl_xor_sync(0xffffffffu, p3, o);
    }
    if (r4 == 0) {
        int m = m0 + wr + q;
        tok[m]      = 1.f / (1.f + expf(-(p0 + bias2)));
        tok[m + 8]  = 1.f / (1.f + expf(-(p1 + bias2)));
        tok[m + 16] = 1.f / (1.f + expf(-(p2 + bias2)));
        tok[m + 24] = 1.f / (1.f + expf(-(p3 + bias2)));
    }
}

// =====================================================================
// Kernel 2: segment-max + mask + per-row stats (warp-shuffle reductions).
// =====================================================================
__global__ void __launch_bounds__(512)
seg_mask_kernel(const int* __restrict__ off,
                const float* __restrict__ labels,
                const float* __restrict__ tok,
                float* __restrict__ out_masked)
{
    const int b = blockIdx.x;
    const int s = threadIdx.x;
    const int lane = s & 31;
    const int warp = s >> 5;
    const int base = b * SEQ;

    float lab  = labels[base + s];
    bool  cont = (off[(size_t)(base + s) * 2] != 0);

    float masked = 0.f;
    if (!cont) {
        float wa = tok[base + s];
        int t = s + 1;
        while (t < SEQ && off[(size_t)(base + t) * 2] != 0) {
            wa = fmaxf(wa, tok[base + t]);
            t++;
        }
        if (lab != -1.0f) masked = wa;
    }
    out_masked[base + s] = masked;

    float z = (lab == 1.0f) ? 1.0f : 0.0f;
    float v_sum = masked;
    float v_max = masked;
    float v_min = (masked == 0.f) ? 1.f : masked;
    float v_lab = lab;
    float v_tl  = (masked - z) * (masked - z);

#pragma unroll
    for (int o = 16; o > 0; o >>= 1) {
        v_sum += __shfl_xor_sync(0xffffffffu, v_sum, o);
        v_max = fmaxf(v_max, __shfl_xor_sync(0xffffffffu, v_max, o));
        v_min = fminf(v_min, __shfl_xor_sync(0xffffffffu, v_min, o));
        v_lab = fmaxf(v_lab, __shfl_xor_sync(0xffffffffu, v_lab, o));
        v_tl  += __shfl_xor_sync(0xffffffffu, v_tl, o);
    }

    __shared__ float ws[16][5];
    if (lane == 0) {
        ws[warp][0] = v_sum; ws[warp][1] = v_max; ws[warp][2] = v_min;
        ws[warp][3] = v_lab; ws[warp][4] = v_tl;
    }
    __syncthreads();

    if (warp == 0) {
        float a0 = (lane < 16) ? ws[lane][0] : 0.f;
        float a1 = (lane < 16) ? ws[lane][1] : -1e30f;
        float a2 = (lane < 16) ? ws[lane][2] :  1e30f;
        float a3 = (lane < 16) ? ws[lane][3] : -1e30f;
        float a4 = (lane < 16) ? ws[lane][4] : 0.f;
#pragma unroll
        for (int o = 8; o > 0; o >>= 1) {
            a0 += __shfl_xor_sync(0xffffffffu, a0, o);
            a1 = fmaxf(a1, __shfl_xor_sync(0xffffffffu, a1, o));
            a2 = fminf(a2, __shfl_xor_sync(0xffffffffu, a2, o));
            a3 = fmaxf(a3, __shfl_xor_sync(0xffffffffu, a3, o));
            a4 += __shfl_xor_sync(0xffffffffu, a4, o);
        }
        if (lane == 0) {
            g_sum[b] = a0; g_maxm[b] = a1; g_minm[b] = a2;
            g_slab[b] = a3; g_tl[b] = a4;
        }
    }
}

// =====================================================================
// Kernel 3: pooling partials + hidden echo (streaming hints).
// grid (BATCH, PSPLIT), 192 threads.
// =====================================================================
__global__ void __launch_bounds__(192)
pool_kernel(const float* __restrict__ hs,
            const float* __restrict__ masked,
            float* __restrict__ out_hidden)
{
    const int b  = blockIdx.x;
    const int ss = blockIdx.y;
    const int tid = threadIdx.x;
    const int SCH = SEQ / PSPLIT;              // 64
    const int s0 = ss * SCH;

    __shared__ float nm[SCH];
    if (tid < SCH) nm[tid] = masked[b * SEQ + s0 + tid];
    __syncthreads();

    const size_t rowbase = (size_t)b * SEQ * HID + (size_t)s0 * HID;
    const float4* hp = reinterpret_cast<const float4*>(hs + rowbase) + tid;
    float* op = out_hidden + rowbase + tid * 4;

    float4 acc = make_float4(0.f, 0.f, 0.f, 0.f);
#pragma unroll 8
    for (int s = 0; s < SCH; s++) {
        float4 v = __ldcs(&hp[(size_t)s * (HID / 4)]);   // stream: no L2 reuse
        float* o = op + (size_t)s * HID;                 // 4B-aligned dest
        __stcs(o + 0, v.x); __stcs(o + 1, v.y);
        __stcs(o + 2, v.z); __stcs(o + 3, v.w);
        float w = nm[s];
        acc.x += v.x * w; acc.y += v.y * w;
        acc.z += v.z * w; acc.w += v.w * w;
    }

    float4* dst = reinterpret_cast<float4*>(
        g_pool_part + ((size_t)ss * BATCH + b) * HID) + tid;
    *dst = acc;
}

// =====================================================================
// Kernel 4: sentence head partials — batch-shared W3.
// grid (5 j-chunks, 8 k-chunks, BATCH/BG b-groups), 64 threads (60 active).
// Each block reads its W3 slice ONCE and applies it to BG pooled vectors.
// =====================================================================
__global__ void __launch_bounds__(64)
sent_part_kernel(const float* __restrict__ W3)
{
    const int jb  = blockIdx.x;          // 0..4   (60 cols each)
    const int ks  = blockIdx.y;          // 0..7   (96 k each)
    const int b0  = blockIdx.z * BG;     // batch group base
    const int tid = threadIdx.x;
    const int k0  = ks * 96;

    // Stage pooled slice: pl[bi][k] for BG batches x 96 k (normalized)
    __shared__ float pl[BG][96];
    for (int i = tid; i < BG * 96; i += 64) {
        int bi = i / 96;
        int k  = i - bi * 96;
        int b  = b0 + bi;
        float v = 0.f;
#pragma unroll
        for (int ss = 0; ss < PSPLIT; ss++)
            v += g_pool_part[((size_t)ss * BATCH + b) * HID + k0 + k];
        pl[bi][k] = v / g_sum[b];
    }
    __syncthreads();

    if (tid < 60) {
        const int j = jb * 60 + tid;
        const float* wp = W3 + (size_t)k0 * CLSH + j;

        float acc[BG];
#pragma unroll
        for (int bi = 0; bi < BG; bi++) acc[bi] = 0.f;

#pragma unroll 4
        for (int k = 0; k < 96; k++) {
            float w = __ldg(&wp[(size_t)k * CLSH]);      // W3 read once per block
#pragma unroll
            for (int bi = 0; bi < BG; bi++)
                acc[bi] += pl[bi][k] * w;                // smem broadcast
        }

#pragma unroll
        for (int bi = 0; bi < BG; bi++)
            g_sent_j[((size_t)(b0 + bi) * 8 + ks) * CLSH + j] = acc[bi];
    }
}

// =====================================================================
// Kernel 5: sentence combine. grid (BATCH), 320 threads.
// =====================================================================
__global__ void __launch_bounds__(320)
sent_comb_kernel(const float* __restrict__ b3,
                 const float* __restrict__ W4,
                 const float* __restrict__ b4,
                 float* __restrict__ out_sent)
{
    const int b = blockIdx.x;
    const int tid = threadIdx.x;

    float v = 0.f;
    if (tid < CLSH) {
        float s = b3[tid];
#pragma unroll
        for (int ks = 0; ks < 8; ks++)
            s += g_sent_j[((size_t)b * 8 + ks) * CLSH + tid];
        v = tanhf(s) * W4[tid];
    }

    __shared__ float red[512];
    red[tid] = v;
    if (tid + 320 < 512) red[tid + 320] = 0.f;
    __syncthreads();
    for (int st = 256; st > 0; st >>= 1) {
        if (tid < st) red[tid] += red[tid + st];
        __syncthreads();
    }
    if (tid == 0) {
        float sv = 1.f / (1.f + expf(-(red[0] + b4[0])));
        g_sent[b] = sv;
        out_sent[b] = sv;
    }
}

// =====================================================================
// Kernel 6: finalize losses.
// =====================================================================
__global__ void __launch_bounds__(64)
final_kernel(float* __restrict__ out)
{
    const int b = threadIdx.x;
    float sl = g_sent[b] - g_slab[b]; sl *= sl;
    float ra = g_minm[b] * g_minm[b];
    float d  = g_maxm[b] - g_slab[b]; float rb = d * d;
    float tl = g_tl[b];

    __shared__ float s1[64], s2[64], s3[64], s4[64];
    s1[b] = sl; s2[b] = tl; s3[b] = ra; s4[b] = rb;
    __syncthreads();
    for (int st = 32; st > 0; st >>= 1) {
        if (b < st) { s1[b] += s1[b+st]; s2[b] += s2[b+st]; s3[b] += s3[b+st]; s4[b] += s4[b+st]; }
        __syncthreads();
    }
    if (b == 0) {
        float sentence = s1[0], token = s2[0], rega = s3[0], regb = s4[0];
        out[0] = sentence + token + 0.01f * (rega + regb);
        out[1] = sentence;
        out[2] = token;
        out[3] = rega;
        out[4] = regb;
    }
}

// =====================================================================
extern "C" void kernel_launch(void* const* d_in, const int* in_sizes, int n_in,
                              void* d_out, int out_size)
{
    const float* hs     = (const float*)d_in[0];
    const int*   off    = (const int*)  d_in[1];
    const float* labels = (const float*)d_in[2];
    const float* W1     = (const float*)d_in[3];
    const float* b1     = (const float*)d_in[4];
    const float* W2     = (const float*)d_in[5];
    const float* b2     = (const float*)d_in[6];
    const float* W3     = (const float*)d_in[7];
    const float* b3     = (const float*)d_in[8];
    const float* W4     = (const float*)d_in[9];
    const float* b4     = (const float*)d_in[10];

    float* out = (float*)d_out;
    float* out_hidden = out + OUT_HID_OFF;
    float* out_masked = out + OUT_MASK_OFF;
    float* out_sent   = out + OUT_SENT_OFF;

    float* tok; cudaGetSymbolAddress((void**)&tok, g_token_att);

    cudaFuncSetAttribute(att_gemm_kernel,
                         cudaFuncAttributeMaxDynamicSharedMemorySize,
                         ATT_SMEM_BYTES);

    // Stage A: token attention head (TF32 MMA, cp.async) — R7-exact
    att_gemm_kernel<<<NTOK / MT, 256, ATT_SMEM_BYTES>>>(hs, W1, b1, W2, b2, tok);

    // Stage B: segment max, mask, row stats
    seg_mask_kernel<<<BATCH, SEQ>>>(off, labels, tok, out_masked);

    // Stage C: pooling partials + hidden echo (streaming hints)
    dim3 pg(BATCH, PSPLIT);
    pool_kernel<<<pg, 192>>>(hs, out_masked, out_hidden);

    // Stage D: sentence head partials — batch-shared W3
    dim3 sg(5, 8, BATCH / BG);
    sent_part_kernel<<<sg, 64>>>(W3);

    // Stage E: sentence combine
    sent_comb_kernel<<<BATCH, 320>>>(b3, W4, b4, out_sent);

    // Stage F: losses
    final_kernel<<<1, 64>>>(out);
}

// round 15
// speedup vs baseline: 1.3594x; 1.0918x over previous
#include <cuda_runtime.h>
#include <cuda_bf16.h>
#include <math.h>

// Problem dims
#define BATCH 64
#define SEQ   512
#define HID   768
#define ATTH  100
#define CLSH  300

#define NTOK (BATCH*SEQ)          // 32768
#define HS_ELEMS (BATCH*SEQ*HID)  // 25165824

// Output layout
#define OUT_HID_OFF  5
#define OUT_MASK_OFF (5 + HS_ELEMS)
#define OUT_SENT_OFF (5 + HS_ELEMS + NTOK)

#define PSPLIT 8

// ---------------- device scratch ----------------
__device__ float g_token_att[NTOK];
__device__ float g_pool_part[PSPLIT * BATCH * HID];
__device__ float g_sent_j[BATCH * 8 * CLSH];
__device__ float g_sum[BATCH];
__device__ float g_maxm[BATCH];
__device__ float g_minm[BATCH];
__device__ float g_slab[BATCH];
__device__ float g_tl[BATCH];
__device__ float g_sent[BATCH];

__device__ __forceinline__ void mma_tf32(float& d0, float& d1, float& d2, float& d3,
                                         unsigned a0, unsigned a1, unsigned a2, unsigned a3,
                                         unsigned b0, unsigned b1) {
    asm volatile(
        "mma.sync.aligned.m16n8k8.row.col.f32.tf32.tf32.f32 "
        "{%0,%1,%2,%3}, {%4,%5,%6,%7}, {%8,%9}, {%0,%1,%2,%3};"
        : "+f"(d0), "+f"(d1), "+f"(d2), "+f"(d3)
        : "r"(a0), "r"(a1), "r"(a2), "r"(a3), "r"(b0), "r"(b1));
}

__device__ __forceinline__ void cp16(float* smem_dst, const float* gsrc) {
    unsigned s = (unsigned)__cvta_generic_to_shared(smem_dst);
    asm volatile("cp.async.cg.shared.global [%0], [%1], 16;" :: "r"(s), "l"(gsrc));
}
__device__ __forceinline__ void cp_commit() {
    asm volatile("cp.async.commit_group;");
}
__device__ __forceinline__ void cp_wait1() {
    asm volatile("cp.async.wait_group 1;");
}

// =====================================================================
// Kernel 1: token-attention head (R7-exact). tf32 MMA, cp.async pipeline.
// =====================================================================
#define MT     256
#define KT     32
#define NT     13
#define KCH    (HID / KT)      // 24
#define ASTR   36
#define WSTR   104
#define STAGES 3
#define A_TILE_FL (MT * ASTR)  // 9216
#define W_TILE_FL (KT * WSTR)  // 3328
#define ATT_SMEM_BYTES (STAGES * (A_TILE_FL + W_TILE_FL) * 4)   // 150528

__global__ void __launch_bounds__(256)
att_gemm_kernel(const float* __restrict__ A,
                const float* __restrict__ W1,
                const float* __restrict__ b1,
                const float* __restrict__ W2,
                const float* __restrict__ b2,
                float* __restrict__ tok)
{
    extern __shared__ float sm[];
    float* Abuf = sm;
    float* Wbuf = sm + STAGES * A_TILE_FL;

    const int tid  = threadIdx.x;
    const int lane = tid & 31;
    const int wid  = tid >> 5;
    const int q    = lane >> 2;
    const int r4   = lane & 3;
    const int m0   = blockIdx.x * MT;
    const int wr   = wid * 32;

    for (int i = tid; i < STAGES * KT * 4; i += 256) {
        int st = i / (KT * 4);
        int r  = (i >> 2) % KT;
        int c  = i & 3;
        Wbuf[st * W_TILE_FL + r * WSTR + ATTH + c] = 0.f;
    }

    float acc0[NT][4], acc1[NT][4];
#pragma unroll
    for (int nt = 0; nt < NT; nt++)
#pragma unroll
        for (int c = 0; c < 4; c++) { acc0[nt][c] = 0.f; acc1[nt][c] = 0.f; }

    auto issue = [&](int st, int k0) {
        float* As = Abuf + st * A_TILE_FL;
        float* Ws = Wbuf + st * W_TILE_FL;
#pragma unroll
        for (int i = 0; i < 8; i++) {
            int f   = i * 256 + tid;
            int row = f >> 3;
            int c16 = f & 7;
            cp16(As + row * ASTR + c16 * 4,
                 A + (size_t)(m0 + row) * HID + k0 + c16 * 4);
        }
#pragma unroll
        for (int i = 0; i < 4; i++) {
            int e = i * 256 + tid;
            if (e < KT * 25) {
                int kr = e / 25;
                int cc = e % 25;
                cp16(Ws + kr * WSTR + cc * 4,
                     W1 + (size_t)(k0 + kr) * ATTH + cc * 4);
            }
        }
    };

    issue(0, 0);       cp_commit();
    issue(1, KT);      cp_commit();

    for (int kc = 0; kc < KCH; kc++) {
        cp_wait1();
        __syncthreads();
        if (kc + 2 < KCH) issue((kc + 2) % STAGES, (kc + 2) * KT);
        cp_commit();

        const float* As = Abuf + (kc % STAGES) * A_TILE_FL;
        const float* Ws = Wbuf + (kc % STAGES) * W_TILE_FL;

#pragma unroll
        for (int ks = 0; ks < 4; ks++) {
            const int k = ks * 8;
            unsigned a00 = __float_as_uint(As[(wr + q     ) * ASTR + k + r4]);
            unsigned a01 = __float_as_uint(As[(wr + q + 8 ) * ASTR + k + r4]);
            unsigned a02 = __float_as_uint(As[(wr + q     ) * ASTR + k + r4 + 4]);
            unsigned a03 = __float_as_uint(As[(wr + q + 8 ) * ASTR + k + r4 + 4]);
            unsigned a10 = __float_as_uint(As[(wr + q + 16) * ASTR + k + r4]);
            unsigned a11 = __float_as_uint(As[(wr + q + 24) * ASTR + k + r4]);
            unsigned a12 = __float_as_uint(As[(wr + q + 16) * ASTR + k + r4 + 4]);
            unsigned a13 = __float_as_uint(As[(wr + q + 24) * ASTR + k + r4 + 4]);
#pragma unroll
            for (int nt = 0; nt < NT; nt++) {
                unsigned b0 = __float_as_uint(Ws[(k + r4    ) * WSTR + nt * 8 + q]);
                unsigned b1 = __float_as_uint(Ws[(k + r4 + 4) * WSTR + nt * 8 + q]);
                mma_tf32(acc0[nt][0], acc0[nt][1], acc0[nt][2], acc0[nt][3],
                         a00, a01, a02, a03, b0, b1);
                mma_tf32(acc1[nt][0], acc1[nt][1], acc1[nt][2], acc1[nt][3],
                         a10, a11, a12, a13, b0, b1);
            }
        }
    }

    const float bias2 = b2[0];
    float p0 = 0.f, p1 = 0.f, p2 = 0.f, p3 = 0.f;
#pragma unroll
    for (int nt = 0; nt < NT; nt++) {
        int j0 = nt * 8 + 2 * r4;
        int j1 = j0 + 1;
        float bb0 = 0.f, bb1 = 0.f, ww0 = 0.f, ww1 = 0.f;
        if (j0 < ATTH) { bb0 = b1[j0]; ww0 = W2[j0]; }
        if (j1 < ATTH) { bb1 = b1[j1]; ww1 = W2[j1]; }
        p0 += tanhf(acc0[nt][0] + bb0) * ww0 + tanhf(acc0[nt][1] + bb1) * ww1;
        p1 += tanhf(acc0[nt][2] + bb0) * ww0 + tanhf(acc0[nt][3] + bb1) * ww1;
        p2 += tanhf(acc1[nt][0] + bb0) * ww0 + tanhf(acc1[nt][1] + bb1) * ww1;
        p3 += tanhf(acc1[nt][2] + bb0) * ww0 + tanhf(acc1[nt][3] + bb1) * ww1;
    }
#pragma unroll
    for (int o = 1; o <= 2; o <<= 1) {
        p0 += __shfl_xor_sync(0xffffffffu, p0, o);
        p1 += __shfl_xor_sync(0xffffffffu, p1, o);
        p2 += __shfl_xor_sync(0xffffffffu, p2, o);
        p3 += __shfl_xor_sync(0xffffffffu, p3, o);
    }
    if (r4 == 0) {
        int m = m0 + wr + q;
        tok[m]      = 1.f / (1.f + expf(-(p0 + bias2)));
        tok[m + 8]  = 1.f / (1.f + expf(-(p1 + bias2)));
        tok[m + 16] = 1.f / (1.f + expf(-(p2 + bias2)));
        tok[m + 24] = 1.f / (1.f + expf(-(p3 + bias2)));
    }
}

// =====================================================================
// Kernel 2: segment-max + mask + per-row stats (warp-shuffle reductions).
// =====================================================================
__global__ void __launch_bounds__(512)
seg_mask_kernel(const int* __restrict__ off,
                const float* __restrict__ labels,
                const float* __restrict__ tok,
                float* __restrict__ out_masked)
{
    const int b = blockIdx.x;
    const int s = threadIdx.x;
    const int lane = s & 31;
    const int warp = s >> 5;
    const int base = b * SEQ;

    float lab  = labels[base + s];
    bool  cont = (off[(size_t)(base + s) * 2] != 0);

    float masked = 0.f;
    if (!cont) {
        float wa = tok[base + s];
        int t = s + 1;
        while (t < SEQ && off[(size_t)(base + t) * 2] != 0) {
            wa = fmaxf(wa, tok[base + t]);
            t++;
        }
        if (lab != -1.0f) masked = wa;
    }
    out_masked[base + s] = masked;

    float z = (lab == 1.0f) ? 1.0f : 0.0f;
    float v_sum = masked;
    float v_max = masked;
    float v_min = (masked == 0.f) ? 1.f : masked;
    float v_lab = lab;
    float v_tl  = (masked - z) * (masked - z);

#pragma unroll
    for (int o = 16; o > 0; o >>= 1) {
        v_sum += __shfl_xor_sync(0xffffffffu, v_sum, o);
        v_max = fmaxf(v_max, __shfl_xor_sync(0xffffffffu, v_max, o));
        v_min = fminf(v_min, __shfl_xor_sync(0xffffffffu, v_min, o));
        v_lab = fmaxf(v_lab, __shfl_xor_sync(0xffffffffu, v_lab, o));
        v_tl  += __shfl_xor_sync(0xffffffffu, v_tl, o);
    }

    __shared__ float ws[16][5];
    if (lane == 0) {
        ws[warp][0] = v_sum; ws[warp][1] = v_max; ws[warp][2] = v_min;
        ws[warp][3] = v_lab; ws[warp][4] = v_tl;
    }
    __syncthreads();

    if (warp == 0) {
        float a0 = (lane < 16) ? ws[lane][0] : 0.f;
        float a1 = (lane < 16) ? ws[lane][1] : -1e30f;
        float a2 = (lane < 16) ? ws[lane][2] :  1e30f;
        float a3 = (lane < 16) ? ws[lane][3] : -1e30f;
        float a4 = (lane < 16) ? ws[lane][4] : 0.f;
#pragma unroll
        for (int o = 8; o > 0; o >>= 1) {
            a0 += __shfl_xor_sync(0xffffffffu, a0, o);
            a1 = fmaxf(a1, __shfl_xor_sync(0xffffffffu, a1, o));
            a2 = fminf(a2, __shfl_xor_sync(0xffffffffu, a2, o));
            a3 = fmaxf(a3, __shfl_xor_sync(0xffffffffu, a3, o));
            a4 += __shfl_xor_sync(0xffffffffu, a4, o);
        }
        if (lane == 0) {
            g_sum[b] = a0; g_maxm[b] = a1; g_minm[b] = a2;
            g_slab[b] = a3; g_tl[b] = a4;
        }
    }
}

// =====================================================================
// Kernel 3: pooling partials + hidden echo (streaming hints — R14 win).
// grid (BATCH, PSPLIT), 192 threads.
// =====================================================================
__global__ void __launch_bounds__(192)
pool_kernel(const float* __restrict__ hs,
            const float* __restrict__ masked,
            float* __restrict__ out_hidden)
{
    const int b  = blockIdx.x;
    const int ss = blockIdx.y;
    const int tid = threadIdx.x;
    const int SCH = SEQ / PSPLIT;              // 64
    const int s0 = ss * SCH;

    __shared__ float nm[SCH];
    if (tid < SCH) nm[tid] = masked[b * SEQ + s0 + tid];
    __syncthreads();

    const size_t rowbase = (size_t)b * SEQ * HID + (size_t)s0 * HID;
    const float4* hp = reinterpret_cast<const float4*>(hs + rowbase) + tid;
    float* op = out_hidden + rowbase + tid * 4;

    float4 acc = make_float4(0.f, 0.f, 0.f, 0.f);
#pragma unroll 8
    for (int s = 0; s < SCH; s++) {
        float4 v = __ldcs(&hp[(size_t)s * (HID / 4)]);   // stream: no L2 reuse
        float* o = op + (size_t)s * HID;                 // 4B-aligned dest
        __stcs(o + 0, v.x); __stcs(o + 1, v.y);
        __stcs(o + 2, v.z); __stcs(o + 3, v.w);
        float w = nm[s];
        acc.x += v.x * w; acc.y += v.y * w;
        acc.z += v.z * w; acc.w += v.w * w;
    }

    float4* dst = reinterpret_cast<float4*>(
        g_pool_part + ((size_t)ss * BATCH + b) * HID) + tid;
    *dst = acc;
}

// =====================================================================
// Kernel 4: sentence head split-k partials (R11-proven, 10.6us).
// grid (BATCH, 8), 320 threads.
// =====================================================================
__global__ void __launch_bounds__(320)
sent_part_kernel(const float* __restrict__ W3)
{
    const int b  = blockIdx.x;
    const int ks = blockIdx.y;
    const int tid = threadIdx.x;
    const int k0 = ks * 96;

    __shared__ float pl[96];
    if (tid < 96) {
        const int h = k0 + tid;
        float v = 0.f;
#pragma unroll
        for (int ss = 0; ss < PSPLIT; ss++)
            v += g_pool_part[((size_t)ss * BATCH + b) * HID + h];
        pl[tid] = v / g_sum[b];
    }
    __syncthreads();

    if (tid < CLSH) {
        const float* wp = W3 + (size_t)k0 * CLSH + tid;
        float a0 = 0.f, a1 = 0.f, a2 = 0.f, a3 = 0.f;
#pragma unroll 6
        for (int k = 0; k < 96; k += 4) {
            a0 += pl[k]     * __ldg(&wp[(size_t)k * CLSH]);
            a1 += pl[k + 1] * __ldg(&wp[(size_t)(k + 1) * CLSH]);
            a2 += pl[k + 2] * __ldg(&wp[(size_t)(k + 2) * CLSH]);
            a3 += pl[k + 3] * __ldg(&wp[(size_t)(k + 3) * CLSH]);
        }
        g_sent_j[((size_t)b * 8 + ks) * CLSH + tid] = (a0 + a1) + (a2 + a3);
    }
}

// =====================================================================
// Kernel 5: sentence combine. grid (BATCH), 320 threads.
// =====================================================================
__global__ void __launch_bounds__(320)
sent_comb_kernel(const float* __restrict__ b3,
                 const float* __restrict__ W4,
                 const float* __restrict__ b4,
                 float* __restrict__ out_sent)
{
    const int b = blockIdx.x;
    const int tid = threadIdx.x;

    float v = 0.f;
    if (tid < CLSH) {
        float s = b3[tid];
#pragma unroll
        for (int ks = 0; ks < 8; ks++)
            s += g_sent_j[((size_t)b * 8 + ks) * CLSH + tid];
        v = tanhf(s) * W4[tid];
    }

    __shared__ float red[512];
    red[tid] = v;
    if (tid + 320 < 512) red[tid + 320] = 0.f;
    __syncthreads();
    for (int st = 256; st > 0; st >>= 1) {
        if (tid < st) red[tid] += red[tid + st];
        __syncthreads();
    }
    if (tid == 0) {
        float sv = 1.f / (1.f + expf(-(red[0] + b4[0])));
        g_sent[b] = sv;
        out_sent[b] = sv;
    }
}

// =====================================================================
// Kernel 6: finalize losses.
// =====================================================================
__global__ void __launch_bounds__(64)
final_kernel(float* __restrict__ out)
{
    const int b = threadIdx.x;
    float sl = g_sent[b] - g_slab[b]; sl *= sl;
    float ra = g_minm[b] * g_minm[b];
    float d  = g_maxm[b] - g_slab[b]; float rb = d * d;
    float tl = g_tl[b];

    __shared__ float s1[64], s2[64], s3[64], s4[64];
    s1[b] = sl; s2[b] = tl; s3[b] = ra; s4[b] = rb;
    __syncthreads();
    for (int st = 32; st > 0; st >>= 1) {
        if (b < st) { s1[b] += s1[b+st]; s2[b] += s2[b+st]; s3[b] += s3[b+st]; s4[b] += s4[b+st]; }
        __syncthreads();
    }
    if (b == 0) {
        float sentence = s1[0], token = s2[0], rega = s3[0], regb = s4[0];
        out[0] = sentence + token + 0.01f * (rega + regb);
        out[1] = sentence;
        out[2] = token;
        out[3] = rega;
        out[4] = regb;
    }
}

// =====================================================================
extern "C" void kernel_launch(void* const* d_in, const int* in_sizes, int n_in,
                              void* d_out, int out_size)
{
    const float* hs     = (const float*)d_in[0];
    const int*   off    = (const int*)  d_in[1];
    const float* labels = (const float*)d_in[2];
    const float* W1     = (const float*)d_in[3];
    const float* b1     = (const float*)d_in[4];
    const float* W2     = (const float*)d_in[5];
    const float* b2     = (const float*)d_in[6];
    const float* W3     = (const float*)d_in[7];
    const float* b3     = (const float*)d_in[8];
    const float* W4     = (const float*)d_in[9];
    const float* b4     = (const float*)d_in[10];

    float* out = (float*)d_out;
    float* out_hidden = out + OUT_HID_OFF;
    float* out_masked = out + OUT_MASK_OFF;
    float* out_sent   = out + OUT_SENT_OFF;

    float* tok; cudaGetSymbolAddress((void**)&tok, g_token_att);

    cudaFuncSetAttribute(att_gemm_kernel,
                         cudaFuncAttributeMaxDynamicSharedMemorySize,
                         ATT_SMEM_BYTES);

    // Stage A: token attention head (TF32 MMA, cp.async) — R7-exact
    att_gemm_kernel<<<NTOK / MT, 256, ATT_SMEM_BYTES>>>(hs, W1, b1, W2, b2, tok);

    // Stage B: segment max, mask, row stats
    seg_mask_kernel<<<BATCH, SEQ>>>(off, labels, tok, out_masked);

    // Stage C: pooling partials + hidden echo (streaming hints)
    dim3 pg(BATCH, PSPLIT);
    pool_kernel<<<pg, 192>>>(hs, out_masked, out_hidden);

    // Stage D: sentence head partials (k-split, R11-proven)
    dim3 sg(BATCH, 8);
    sent_part_kernel<<<sg, 320>>>(W3);

    // Stage E: sentence combine
    sent_comb_kernel<<<BATCH, 320>>>(b3, W4, b4, out_sent);

    // Stage F: losses
    final_kernel<<<1, 64>>>(out);
}

// round 16
// speedup vs baseline: 1.3860x; 1.0195x over previous
#include <cuda_runtime.h>
#include <cuda_bf16.h>
#include <math.h>

// Problem dims
#define BATCH 64
#define SEQ   512
#define HID   768
#define ATTH  100
#define CLSH  300

#define NTOK (BATCH*SEQ)          // 32768
#define HS_ELEMS (BATCH*SEQ*HID)  // 25165824

// Output layout
#define OUT_HID_OFF  5
#define OUT_MASK_OFF (5 + HS_ELEMS)
#define OUT_SENT_OFF (5 + HS_ELEMS + NTOK)

#define PSPLIT 8
#define SCH    (SEQ / PSPLIT)     // 64 tokens per pool chunk

// ---------------- device scratch ----------------
__device__ float g_token_att[NTOK];
__device__ float g_pool_part[PSPLIT * BATCH * HID];
__device__ float g_sent_j[BATCH * 8 * CLSH];
__device__ float g_csum [BATCH * PSPLIT];   // chunk stats
__device__ float g_cmax [BATCH * PSPLIT];
__device__ float g_cmin [BATCH * PSPLIT];
__device__ float g_cslab[BATCH * PSPLIT];
__device__ float g_ctl  [BATCH * PSPLIT];
__device__ float g_sent[BATCH];

__device__ __forceinline__ void mma_tf32(float& d0, float& d1, float& d2, float& d3,
                                         unsigned a0, unsigned a1, unsigned a2, unsigned a3,
                                         unsigned b0, unsigned b1) {
    asm volatile(
        "mma.sync.aligned.m16n8k8.row.col.f32.tf32.tf32.f32 "
        "{%0,%1,%2,%3}, {%4,%5,%6,%7}, {%8,%9}, {%0,%1,%2,%3};"
        : "+f"(d0), "+f"(d1), "+f"(d2), "+f"(d3)
        : "r"(a0), "r"(a1), "r"(a2), "r"(a3), "r"(b0), "r"(b1));
}

__device__ __forceinline__ void cp16(float* smem_dst, const float* gsrc) {
    unsigned s = (unsigned)__cvta_generic_to_shared(smem_dst);
    asm volatile("cp.async.cg.shared.global [%0], [%1], 16;" :: "r"(s), "l"(gsrc));
}
__device__ __forceinline__ void cp_commit() {
    asm volatile("cp.async.commit_group;");
}
__device__ __forceinline__ void cp_wait1() {
    asm volatile("cp.async.wait_group 1;");
}

// =====================================================================
// Kernel 1: token-attention head (R7-exact). tf32 MMA, cp.async pipeline.
// =====================================================================
#define MT     256
#define KT     32
#define NT     13
#define KCH    (HID / KT)      // 24
#define ASTR   36
#define WSTR   104
#define STAGES 3
#define A_TILE_FL (MT * ASTR)  // 9216
#define W_TILE_FL (KT * WSTR)  // 3328
#define ATT_SMEM_BYTES (STAGES * (A_TILE_FL + W_TILE_FL) * 4)   // 150528

__global__ void __launch_bounds__(256)
att_gemm_kernel(const float* __restrict__ A,
                const float* __restrict__ W1,
                const float* __restrict__ b1,
                const float* __restrict__ W2,
                const float* __restrict__ b2,
                float* __restrict__ tok)
{
    extern __shared__ float sm[];
    float* Abuf = sm;
    float* Wbuf = sm + STAGES * A_TILE_FL;

    const int tid  = threadIdx.x;
    const int lane = tid & 31;
    const int wid  = tid >> 5;
    const int q    = lane >> 2;
    const int r4   = lane & 3;
    const int m0   = blockIdx.x * MT;
    const int wr   = wid * 32;

    for (int i = tid; i < STAGES * KT * 4; i += 256) {
        int st = i / (KT * 4);
        int r  = (i >> 2) % KT;
        int c  = i & 3;
        Wbuf[st * W_TILE_FL + r * WSTR + ATTH + c] = 0.f;
    }

    float acc0[NT][4], acc1[NT][4];
#pragma unroll
    for (int nt = 0; nt < NT; nt++)
#pragma unroll
        for (int c = 0; c < 4; c++) { acc0[nt][c] = 0.f; acc1[nt][c] = 0.f; }

    auto issue = [&](int st, int k0) {
        float* As = Abuf + st * A_TILE_FL;
        float* Ws = Wbuf + st * W_TILE_FL;
#pragma unroll
        for (int i = 0; i < 8; i++) {
            int f   = i * 256 + tid;
            int row = f >> 3;
            int c16 = f & 7;
            cp16(As + row * ASTR + c16 * 4,
                 A + (size_t)(m0 + row) * HID + k0 + c16 * 4);
        }
#pragma unroll
        for (int i = 0; i < 4; i++) {
            int e = i * 256 + tid;
            if (e < KT * 25) {
                int kr = e / 25;
                int cc = e % 25;
                cp16(Ws + kr * WSTR + cc * 4,
                     W1 + (size_t)(k0 + kr) * ATTH + cc * 4);
            }
        }
    };

    issue(0, 0);       cp_commit();
    issue(1, KT);      cp_commit();

    for (int kc = 0; kc < KCH; kc++) {
        cp_wait1();
        __syncthreads();
        if (kc + 2 < KCH) issue((kc + 2) % STAGES, (kc + 2) * KT);
        cp_commit();

        const float* As = Abuf + (kc % STAGES) * A_TILE_FL;
        const float* Ws = Wbuf + (kc % STAGES) * W_TILE_FL;

#pragma unroll
        for (int ks = 0; ks < 4; ks++) {
            const int k = ks * 8;
            unsigned a00 = __float_as_uint(As[(wr + q     ) * ASTR + k + r4]);
            unsigned a01 = __float_as_uint(As[(wr + q + 8 ) * ASTR + k + r4]);
            unsigned a02 = __float_as_uint(As[(wr + q     ) * ASTR + k + r4 + 4]);
            unsigned a03 = __float_as_uint(As[(wr + q + 8 ) * ASTR + k + r4 + 4]);
            unsigned a10 = __float_as_uint(As[(wr + q + 16) * ASTR + k + r4]);
            unsigned a11 = __float_as_uint(As[(wr + q + 24) * ASTR + k + r4]);
            unsigned a12 = __float_as_uint(As[(wr + q + 16) * ASTR + k + r4 + 4]);
            unsigned a13 = __float_as_uint(As[(wr + q + 24) * ASTR + k + r4 + 4]);
#pragma unroll
            for (int nt = 0; nt < NT; nt++) {
                unsigned b0 = __float_as_uint(Ws[(k + r4    ) * WSTR + nt * 8 + q]);
                unsigned b1 = __float_as_uint(Ws[(k + r4 + 4) * WSTR + nt * 8 + q]);
                mma_tf32(acc0[nt][0], acc0[nt][1], acc0[nt][2], acc0[nt][3],
                         a00, a01, a02, a03, b0, b1);
                mma_tf32(acc1[nt][0], acc1[nt][1], acc1[nt][2], acc1[nt][3],
                         a10, a11, a12, a13, b0, b1);
            }
        }
    }

    const float bias2 = b2[0];
    float p0 = 0.f, p1 = 0.f, p2 = 0.f, p3 = 0.f;
#pragma unroll
    for (int nt = 0; nt < NT; nt++) {
        int j0 = nt * 8 + 2 * r4;
        int j1 = j0 + 1;
        float bb0 = 0.f, bb1 = 0.f, ww0 = 0.f, ww1 = 0.f;
        if (j0 < ATTH) { bb0 = b1[j0]; ww0 = W2[j0]; }
        if (j1 < ATTH) { bb1 = b1[j1]; ww1 = W2[j1]; }
        p0 += tanhf(acc0[nt][0] + bb0) * ww0 + tanhf(acc0[nt][1] + bb1) * ww1;
        p1 += tanhf(acc0[nt][2] + bb0) * ww0 + tanhf(acc0[nt][3] + bb1) * ww1;
        p2 += tanhf(acc1[nt][0] + bb0) * ww0 + tanhf(acc1[nt][1] + bb1) * ww1;
        p3 += tanhf(acc1[nt][2] + bb0) * ww0 + tanhf(acc1[nt][3] + bb1) * ww1;
    }
#pragma unroll
    for (int o = 1; o <= 2; o <<= 1) {
        p0 += __shfl_xor_sync(0xffffffffu, p0, o);
        p1 += __shfl_xor_sync(0xffffffffu, p1, o);
        p2 += __shfl_xor_sync(0xffffffffu, p2, o);
        p3 += __shfl_xor_sync(0xffffffffu, p3, o);
    }
    if (r4 == 0) {
        int m = m0 + wr + q;
        tok[m]      = 1.f / (1.f + expf(-(p0 + bias2)));
        tok[m + 8]  = 1.f / (1.f + expf(-(p1 + bias2)));
        tok[m + 16] = 1.f / (1.f + expf(-(p2 + bias2)));
        tok[m + 24] = 1.f / (1.f + expf(-(p3 + bias2)));
    }
}

// =====================================================================
// Kernel 2: fused segment-mask + pooling partials + hidden echo.
// grid (BATCH, PSPLIT), 192 threads.
// Threads 0..63 compute masked for their token (scan may cross chunk
// boundary; tok is globally complete). Chunk stats -> scratch.
// Then all 192 threads do the pooling + echo pass.
// =====================================================================
__global__ void __launch_bounds__(192)
pool_kernel(const float* __restrict__ hs,
            const int*   __restrict__ off,
            const float* __restrict__ labels,
            const float* __restrict__ tok,
            float* __restrict__ out_masked,
            float* __restrict__ out_hidden)
{
    const int b  = blockIdx.x;
    const int ss = blockIdx.y;
    const int tid = threadIdx.x;
    const int s0 = ss * SCH;
    const int base = b * SEQ;

    __shared__ float nm[SCH];
    __shared__ float ws[2][5];

    if (tid < SCH) {
        const int s = s0 + tid;
        float lab  = labels[base + s];
        bool  cont = (off[(size_t)(base + s) * 2] != 0);

        float masked = 0.f;
        if (!cont) {
            float wa = tok[base + s];
            int t = s + 1;
            while (t < SEQ && off[(size_t)(base + t) * 2] != 0) {
                wa = fmaxf(wa, tok[base + t]);
                t++;
            }
            if (lab != -1.0f) masked = wa;
        }
        out_masked[base + s] = masked;
        nm[tid] = masked;

        // chunk stats
        float z = (lab == 1.0f) ? 1.0f : 0.0f;
        float v_sum = masked;
        float v_max = masked;
        float v_min = (masked == 0.f) ? 1.f : masked;
        float v_lab = lab;
        float v_tl  = (masked - z) * (masked - z);

#pragma unroll
        for (int o = 16; o > 0; o >>= 1) {
            v_sum += __shfl_xor_sync(0xffffffffu, v_sum, o);
            v_max = fmaxf(v_max, __shfl_xor_sync(0xffffffffu, v_max, o));
            v_min = fminf(v_min, __shfl_xor_sync(0xffffffffu, v_min, o));
            v_lab = fmaxf(v_lab, __shfl_xor_sync(0xffffffffu, v_lab, o));
            v_tl  += __shfl_xor_sync(0xffffffffu, v_tl, o);
        }
        if ((tid & 31) == 0) {
            int w = tid >> 5;           // 0 or 1
            ws[w][0] = v_sum; ws[w][1] = v_max; ws[w][2] = v_min;
            ws[w][3] = v_lab; ws[w][4] = v_tl;
        }
    }
    __syncthreads();

    if (tid == 0) {
        int ci = b * PSPLIT + ss;
        g_csum [ci] = ws[0][0] + ws[1][0];
        g_cmax [ci] = fmaxf(ws[0][1], ws[1][1]);
        g_cmin [ci] = fminf(ws[0][2], ws[1][2]);
        g_cslab[ci] = fmaxf(ws[0][3], ws[1][3]);
        g_ctl  [ci] = ws[0][4] + ws[1][4];
    }

    // pooling + echo (streaming hints)
    const size_t rowbase = (size_t)b * SEQ * HID + (size_t)s0 * HID;
    const float4* hp = reinterpret_cast<const float4*>(hs + rowbase) + tid;
    float* op = out_hidden + rowbase + tid * 4;

    float4 acc = make_float4(0.f, 0.f, 0.f, 0.f);
#pragma unroll 8
    for (int s = 0; s < SCH; s++) {
        float4 v = __ldcs(&hp[(size_t)s * (HID / 4)]);
        float* o = op + (size_t)s * HID;                 // 4B-aligned dest
        __stcs(o + 0, v.x); __stcs(o + 1, v.y);
        __stcs(o + 2, v.z); __stcs(o + 3, v.w);
        float w = nm[s];
        acc.x += v.x * w; acc.y += v.y * w;
        acc.z += v.z * w; acc.w += v.w * w;
    }

    float4* dst = reinterpret_cast<float4*>(
        g_pool_part + ((size_t)ss * BATCH + b) * HID) + tid;
    *dst = acc;
}

// =====================================================================
// Kernel 3: sentence head split-k partials. grid (BATCH, 8), 320 threads.
// g_sum reconstructed from chunk sums.
// =====================================================================
__global__ void __launch_bounds__(320)
sent_part_kernel(const float* __restrict__ W3)
{
    const int b  = blockIdx.x;
    const int ks = blockIdx.y;
    const int tid = threadIdx.x;
    const int k0 = ks * 96;

    __shared__ float pl[96];
    __shared__ float s_inv;

    if (tid == 0) {
        float sum = 0.f;
#pragma unroll
        for (int ss = 0; ss < PSPLIT; ss++)
            sum += g_csum[b * PSPLIT + ss];
        s_inv = 1.0f / sum;
    }
    if (tid < 96) {
        const int h = k0 + tid;
        float v = 0.f;
#pragma unroll
        for (int ss = 0; ss < PSPLIT; ss++)
            v += g_pool_part[((size_t)ss * BATCH + b) * HID + h];
        pl[tid] = v;            // normalize after sync via s_inv
    }
    __syncthreads();
    if (tid < 96) pl[tid] *= s_inv;
    __syncthreads();

    if (tid < CLSH) {
        const float* wp = W3 + (size_t)k0 * CLSH + tid;
        float a0 = 0.f, a1 = 0.f, a2 = 0.f, a3 = 0.f;
#pragma unroll 6
        for (int k = 0; k < 96; k += 4) {
            a0 += pl[k]     * __ldg(&wp[(size_t)k * CLSH]);
            a1 += pl[k + 1] * __ldg(&wp[(size_t)(k + 1) * CLSH]);
            a2 += pl[k + 2] * __ldg(&wp[(size_t)(k + 2) * CLSH]);
            a3 += pl[k + 3] * __ldg(&wp[(size_t)(k + 3) * CLSH]);
        }
        g_sent_j[((size_t)b * 8 + ks) * CLSH + tid] = (a0 + a1) + (a2 + a3);
    }
}

// =====================================================================
// Kernel 4: sentence combine. grid (BATCH), 320 threads.
// =====================================================================
__global__ void __launch_bounds__(320)
sent_comb_kernel(const float* __restrict__ b3,
                 const float* __restrict__ W4,
                 const float* __restrict__ b4,
                 float* __restrict__ out_sent)
{
    const int b = blockIdx.x;
    const int tid = threadIdx.x;

    float v = 0.f;
    if (tid < CLSH) {
        float s = b3[tid];
#pragma unroll
        for (int ks = 0; ks < 8; ks++)
            s += g_sent_j[((size_t)b * 8 + ks) * CLSH + tid];
        v = tanhf(s) * W4[tid];
    }

    __shared__ float red[512];
    red[tid] = v;
    if (tid + 320 < 512) red[tid + 320] = 0.f;
    __syncthreads();
    for (int st = 256; st > 0; st >>= 1) {
        if (tid < st) red[tid] += red[tid + st];
        __syncthreads();
    }
    if (tid == 0) {
        float sv = 1.f / (1.f + expf(-(red[0] + b4[0])));
        g_sent[b] = sv;
        out_sent[b] = sv;
    }
}

// =====================================================================
// Kernel 5: finalize losses (reduces chunk stats 8-way per batch).
// =====================================================================
__global__ void __launch_bounds__(64)
final_kernel(float* __restrict__ out)
{
    const int b = threadIdx.x;

    float maxm = -1e30f, minm = 1e30f, slab = -1e30f, tl = 0.f;
#pragma unroll
    for (int ss = 0; ss < PSPLIT; ss++) {
        int ci = b * PSPLIT + ss;
        maxm = fmaxf(maxm, g_cmax[ci]);
        minm = fminf(minm, g_cmin[ci]);
        slab = fmaxf(slab, g_cslab[ci]);
        tl  += g_ctl[ci];
    }

    float sl = g_sent[b] - slab; sl *= sl;
    float ra = minm * minm;
    float d  = maxm - slab; float rb = d * d;

    __shared__ float s1[64], s2[64], s3[64], s4[64];
    s1[b] = sl; s2[b] = tl; s3[b] = ra; s4[b] = rb;
    __syncthreads();
    for (int st = 32; st > 0; st >>= 1) {
        if (b < st) { s1[b] += s1[b+st]; s2[b] += s2[b+st]; s3[b] += s3[b+st]; s4[b] += s4[b+st]; }
        __syncthreads();
    }
    if (b == 0) {
        float sentence = s1[0], token = s2[0], rega = s3[0], regb = s4[0];
        out[0] = sentence + token + 0.01f * (rega + regb);
        out[1] = sentence;
        out[2] = token;
        out[3] = rega;
        out[4] = regb;
    }
}

// =====================================================================
extern "C" void kernel_launch(void* const* d_in, const int* in_sizes, int n_in,
                              void* d_out, int out_size)
{
    const float* hs     = (const float*)d_in[0];
    const int*   off    = (const int*)  d_in[1];
    const float* labels = (const float*)d_in[2];
    const float* W1     = (const float*)d_in[3];
    const float* b1     = (const float*)d_in[4];
    const float* W2     = (const float*)d_in[5];
    const float* b2     = (const float*)d_in[6];
    const float* W3     = (const float*)d_in[7];
    const float* b3     = (const float*)d_in[8];
    const float* W4     = (const float*)d_in[9];
    const float* b4     = (const float*)d_in[10];

    float* out = (float*)d_out;
    float* out_hidden = out + OUT_HID_OFF;
    float* out_masked = out + OUT_MASK_OFF;
    float* out_sent   = out + OUT_SENT_OFF;

    float* tok; cudaGetSymbolAddress((void**)&tok, g_token_att);

    cudaFuncSetAttribute(att_gemm_kernel,
                         cudaFuncAttributeMaxDynamicSharedMemorySize,
                         ATT_SMEM_BYTES);

    // Stage A: token attention head (TF32 MMA, cp.async)
    att_gemm_kernel<<<NTOK / MT, 256, ATT_SMEM_BYTES>>>(hs, W1, b1, W2, b2, tok);

    // Stage B: fused segment-mask + pooling partials + hidden echo
    dim3 pg(BATCH, PSPLIT);
    pool_kernel<<<pg, 192>>>(hs, off, labels, tok, out_masked, out_hidden);

    // Stage C: sentence head partials (k-split)
    dim3 sg(BATCH, 8);
    sent_part_kernel<<<sg, 320>>>(W3);

    // Stage D: sentence combine
    sent_comb_kernel<<<BATCH, 320>>>(b3, W4, b4, out_sent);

    // Stage E: losses
    final_kernel<<<1, 64>>>(out);
}

// round 17
// speedup vs baseline: 1.3898x; 1.0028x over previous
#include <cuda_runtime.h>
#include <cuda_bf16.h>
#include <math.h>

// Problem dims
#define BATCH 64
#define SEQ   512
#define HID   768
#define ATTH  100
#define CLSH  300

#define NTOK (BATCH*SEQ)          // 32768
#define HS_ELEMS (BATCH*SEQ*HID)  // 25165824

// Output layout
#define OUT_HID_OFF  5
#define OUT_MASK_OFF (5 + HS_ELEMS)
#define OUT_SENT_OFF (5 + HS_ELEMS + NTOK)

#define PSPLIT 8
#define SCH    (SEQ / PSPLIT)     // 64 tokens per pool chunk
#define JSPLIT 8
#define JCH    38                 // ceil(300/8)

// ---------------- device scratch ----------------
__device__ float g_token_att[NTOK];
__device__ float g_pool_part[PSPLIT * BATCH * HID];
__device__ float g_sentp[BATCH * JSPLIT];   // scalar sentence partials
__device__ float g_csum [BATCH * PSPLIT];   // chunk stats
__device__ float g_cmax [BATCH * PSPLIT];
__device__ float g_cmin [BATCH * PSPLIT];
__device__ float g_cslab[BATCH * PSPLIT];
__device__ float g_ctl  [BATCH * PSPLIT];

__device__ __forceinline__ void mma_tf32(float& d0, float& d1, float& d2, float& d3,
                                         unsigned a0, unsigned a1, unsigned a2, unsigned a3,
                                         unsigned b0, unsigned b1) {
    asm volatile(
        "mma.sync.aligned.m16n8k8.row.col.f32.tf32.tf32.f32 "
        "{%0,%1,%2,%3}, {%4,%5,%6,%7}, {%8,%9}, {%0,%1,%2,%3};"
        : "+f"(d0), "+f"(d1), "+f"(d2), "+f"(d3)
        : "r"(a0), "r"(a1), "r"(a2), "r"(a3), "r"(b0), "r"(b1));
}

__device__ __forceinline__ void cp16(float* smem_dst, const float* gsrc) {
    unsigned s = (unsigned)__cvta_generic_to_shared(smem_dst);
    asm volatile("cp.async.cg.shared.global [%0], [%1], 16;" :: "r"(s), "l"(gsrc));
}
__device__ __forceinline__ void cp_commit() {
    asm volatile("cp.async.commit_group;");
}
__device__ __forceinline__ void cp_wait1() {
    asm volatile("cp.async.wait_group 1;");
}

// =====================================================================
// Kernel 1: token-attention head (R7-exact). tf32 MMA, cp.async pipeline.
// =====================================================================
#define MT     256
#define KT     32
#define NT     13
#define KCH    (HID / KT)      // 24
#define ASTR   36
#define WSTR   104
#define STAGES 3
#define A_TILE_FL (MT * ASTR)  // 9216
#define W_TILE_FL (KT * WSTR)  // 3328
#define ATT_SMEM_BYTES (STAGES * (A_TILE_FL + W_TILE_FL) * 4)   // 150528

__global__ void __launch_bounds__(256)
att_gemm_kernel(const float* __restrict__ A,
                const float* __restrict__ W1,
                const float* __restrict__ b1,
                const float* __restrict__ W2,
                const float* __restrict__ b2,
                float* __restrict__ tok)
{
    extern __shared__ float sm[];
    float* Abuf = sm;
    float* Wbuf = sm + STAGES * A_TILE_FL;

    const int tid  = threadIdx.x;
    const int lane = tid & 31;
    const int wid  = tid >> 5;
    const int q    = lane >> 2;
    const int r4   = lane & 3;
    const int m0   = blockIdx.x * MT;
    const int wr   = wid * 32;

    for (int i = tid; i < STAGES * KT * 4; i += 256) {
        int st = i / (KT * 4);
        int r  = (i >> 2) % KT;
        int c  = i & 3;
        Wbuf[st * W_TILE_FL + r * WSTR + ATTH + c] = 0.f;
    }

    float acc0[NT][4], acc1[NT][4];
#pragma unroll
    for (int nt = 0; nt < NT; nt++)
#pragma unroll
        for (int c = 0; c < 4; c++) { acc0[nt][c] = 0.f; acc1[nt][c] = 0.f; }

    auto issue = [&](int st, int k0) {
        float* As = Abuf + st * A_TILE_FL;
        float* Ws = Wbuf + st * W_TILE_FL;
#pragma unroll
        for (int i = 0; i < 8; i++) {
            int f   = i * 256 + tid;
            int row = f >> 3;
            int c16 = f & 7;
            cp16(As + row * ASTR + c16 * 4,
                 A + (size_t)(m0 + row) * HID + k0 + c16 * 4);
        }
#pragma unroll
        for (int i = 0; i < 4; i++) {
            int e = i * 256 + tid;
            if (e < KT * 25) {
                int kr = e / 25;
                int cc = e % 25;
                cp16(Ws + kr * WSTR + cc * 4,
                     W1 + (size_t)(k0 + kr) * ATTH + cc * 4);
            }
        }
    };

    issue(0, 0);       cp_commit();
    issue(1, KT);      cp_commit();

    for (int kc = 0; kc < KCH; kc++) {
        cp_wait1();
        __syncthreads();
        if (kc + 2 < KCH) issue((kc + 2) % STAGES, (kc + 2) * KT);
        cp_commit();

        const float* As = Abuf + (kc % STAGES) * A_TILE_FL;
        const float* Ws = Wbuf + (kc % STAGES) * W_TILE_FL;

#pragma unroll
        for (int ks = 0; ks < 4; ks++) {
            const int k = ks * 8;
            unsigned a00 = __float_as_uint(As[(wr + q     ) * ASTR + k + r4]);
            unsigned a01 = __float_as_uint(As[(wr + q + 8 ) * ASTR + k + r4]);
            unsigned a02 = __float_as_uint(As[(wr + q     ) * ASTR + k + r4 + 4]);
            unsigned a03 = __float_as_uint(As[(wr + q + 8 ) * ASTR + k + r4 + 4]);
            unsigned a10 = __float_as_uint(As[(wr + q + 16) * ASTR + k + r4]);
            unsigned a11 = __float_as_uint(As[(wr + q + 24) * ASTR + k + r4]);
            unsigned a12 = __float_as_uint(As[(wr + q + 16) * ASTR + k + r4 + 4]);
            unsigned a13 = __float_as_uint(As[(wr + q + 24) * ASTR + k + r4 + 4]);
#pragma unroll
            for (int nt = 0; nt < NT; nt++) {
                unsigned b0 = __float_as_uint(Ws[(k + r4    ) * WSTR + nt * 8 + q]);
                unsigned b1 = __float_as_uint(Ws[(k + r4 + 4) * WSTR + nt * 8 + q]);
                mma_tf32(acc0[nt][0], acc0[nt][1], acc0[nt][2], acc0[nt][3],
                         a00, a01, a02, a03, b0, b1);
                mma_tf32(acc1[nt][0], acc1[nt][1], acc1[nt][2], acc1[nt][3],
                         a10, a11, a12, a13, b0, b1);
            }
        }
    }

    const float bias2 = b2[0];
    float p0 = 0.f, p1 = 0.f, p2 = 0.f, p3 = 0.f;
#pragma unroll
    for (int nt = 0; nt < NT; nt++) {
        int j0 = nt * 8 + 2 * r4;
        int j1 = j0 + 1;
        float bb0 = 0.f, bb1 = 0.f, ww0 = 0.f, ww1 = 0.f;
        if (j0 < ATTH) { bb0 = b1[j0]; ww0 = W2[j0]; }
        if (j1 < ATTH) { bb1 = b1[j1]; ww1 = W2[j1]; }
        p0 += tanhf(acc0[nt][0] + bb0) * ww0 + tanhf(acc0[nt][1] + bb1) * ww1;
        p1 += tanhf(acc0[nt][2] + bb0) * ww0 + tanhf(acc0[nt][3] + bb1) * ww1;
        p2 += tanhf(acc1[nt][0] + bb0) * ww0 + tanhf(acc1[nt][1] + bb1) * ww1;
        p3 += tanhf(acc1[nt][2] + bb0) * ww0 + tanhf(acc1[nt][3] + bb1) * ww1;
    }
#pragma unroll
    for (int o = 1; o <= 2; o <<= 1) {
        p0 += __shfl_xor_sync(0xffffffffu, p0, o);
        p1 += __shfl_xor_sync(0xffffffffu, p1, o);
        p2 += __shfl_xor_sync(0xffffffffu, p2, o);
        p3 += __shfl_xor_sync(0xffffffffu, p3, o);
    }
    if (r4 == 0) {
        int m = m0 + wr + q;
        tok[m]      = 1.f / (1.f + expf(-(p0 + bias2)));
        tok[m + 8]  = 1.f / (1.f + expf(-(p1 + bias2)));
        tok[m + 16] = 1.f / (1.f + expf(-(p2 + bias2)));
        tok[m + 24] = 1.f / (1.f + expf(-(p3 + bias2)));
    }
}

// =====================================================================
// Kernel 2: fused segment-mask + pooling partials + hidden echo (R16).
// grid (BATCH, PSPLIT), 192 threads.
// =====================================================================
__global__ void __launch_bounds__(192)
pool_kernel(const float* __restrict__ hs,
            const int*   __restrict__ off,
            const float* __restrict__ labels,
            const float* __restrict__ tok,
            float* __restrict__ out_masked,
            float* __restrict__ out_hidden)
{
    const int b  = blockIdx.x;
    const int ss = blockIdx.y;
    const int tid = threadIdx.x;
    const int s0 = ss * SCH;
    const int base = b * SEQ;

    __shared__ float nm[SCH];
    __shared__ float ws[2][5];

    if (tid < SCH) {
        const int s = s0 + tid;
        float lab  = labels[base + s];
        bool  cont = (off[(size_t)(base + s) * 2] != 0);

        float masked = 0.f;
        if (!cont) {
            float wa = tok[base + s];
            int t = s + 1;
            while (t < SEQ && off[(size_t)(base + t) * 2] != 0) {
                wa = fmaxf(wa, tok[base + t]);
                t++;
            }
            if (lab != -1.0f) masked = wa;
        }
        out_masked[base + s] = masked;
        nm[tid] = masked;

        float z = (lab == 1.0f) ? 1.0f : 0.0f;
        float v_sum = masked;
        float v_max = masked;
        float v_min = (masked == 0.f) ? 1.f : masked;
        float v_lab = lab;
        float v_tl  = (masked - z) * (masked - z);

#pragma unroll
        for (int o = 16; o > 0; o >>= 1) {
            v_sum += __shfl_xor_sync(0xffffffffu, v_sum, o);
            v_max = fmaxf(v_max, __shfl_xor_sync(0xffffffffu, v_max, o));
            v_min = fminf(v_min, __shfl_xor_sync(0xffffffffu, v_min, o));
            v_lab = fmaxf(v_lab, __shfl_xor_sync(0xffffffffu, v_lab, o));
            v_tl  += __shfl_xor_sync(0xffffffffu, v_tl, o);
        }
        if ((tid & 31) == 0) {
            int w = tid >> 5;
            ws[w][0] = v_sum; ws[w][1] = v_max; ws[w][2] = v_min;
            ws[w][3] = v_lab; ws[w][4] = v_tl;
        }
    }
    __syncthreads();

    if (tid == 0) {
        int ci = b * PSPLIT + ss;
        g_csum [ci] = ws[0][0] + ws[1][0];
        g_cmax [ci] = fmaxf(ws[0][1], ws[1][1]);
        g_cmin [ci] = fminf(ws[0][2], ws[1][2]);
        g_cslab[ci] = fmaxf(ws[0][3], ws[1][3]);
        g_ctl  [ci] = ws[0][4] + ws[1][4];
    }

    const size_t rowbase = (size_t)b * SEQ * HID + (size_t)s0 * HID;
    const float4* hp = reinterpret_cast<const float4*>(hs + rowbase) + tid;
    float* op = out_hidden + rowbase + tid * 4;

    float4 acc = make_float4(0.f, 0.f, 0.f, 0.f);
#pragma unroll 8
    for (int s = 0; s < SCH; s++) {
        float4 v = __ldcs(&hp[(size_t)s * (HID / 4)]);
        float* o = op + (size_t)s * HID;
        __stcs(o + 0, v.x); __stcs(o + 1, v.y);
        __stcs(o + 2, v.z); __stcs(o + 3, v.w);
        float w = nm[s];
        acc.x += v.x * w; acc.y += v.y * w;
        acc.z += v.z * w; acc.w += v.w * w;
    }

    float4* dst = reinterpret_cast<float4*>(
        g_pool_part + ((size_t)ss * BATCH + b) * HID) + tid;
    *dst = acc;
}

// =====================================================================
// Kernel 3: sentence head j-split — produces scalar partials directly.
// grid (BATCH, JSPLIT), 320 threads. Block (b, jb): 38 j-cols x 8 k-subs.
// Normalization folded into the final scalar (linearity).
// =====================================================================
__global__ void __launch_bounds__(320)
sent_part_kernel(const float* __restrict__ W3,
                 const float* __restrict__ b3,
                 const float* __restrict__ W4)
{
    const int b   = blockIdx.x;
    const int jb  = blockIdx.y;
    const int tid = threadIdx.x;

    __shared__ float pl[HID];           // unnormalized pooled
    __shared__ float s_inv_sh;
    __shared__ float part[JCH][9];      // [jl][ksub], padded
    __shared__ float red[64];

    if (tid == 0) {
        float sum = 0.f;
#pragma unroll
        for (int ss = 0; ss < PSPLIT; ss++)
            sum += g_csum[b * PSPLIT + ss];
        s_inv_sh = 1.0f / sum;
    }
    for (int h = tid; h < HID; h += 320) {
        float v = 0.f;
#pragma unroll
        for (int ss = 0; ss < PSPLIT; ss++)
            v += g_pool_part[((size_t)ss * BATCH + b) * HID + h];
        pl[h] = v;
    }
    __syncthreads();

    if (tid < JCH * 8) {                 // 304 threads
        const int jl   = tid % JCH;
        const int ksub = tid / JCH;      // 0..7
        const int j    = jb * JCH + jl;
        const int k0   = ksub * 96;
        float a0 = 0.f, a1 = 0.f, a2 = 0.f, a3 = 0.f;
        if (j < CLSH) {
            const float* wp = W3 + (size_t)k0 * CLSH + j;
            const float* pk = pl + k0;
#pragma unroll 6
            for (int k = 0; k < 96; k += 4) {
                a0 += pk[k]     * __ldg(&wp[(size_t)k * CLSH]);
                a1 += pk[k + 1] * __ldg(&wp[(size_t)(k + 1) * CLSH]);
                a2 += pk[k + 2] * __ldg(&wp[(size_t)(k + 2) * CLSH]);
                a3 += pk[k + 3] * __ldg(&wp[(size_t)(k + 3) * CLSH]);
            }
        }
        part[jl][ksub] = (a0 + a1) + (a2 + a3);
    }
    __syncthreads();

    float v = 0.f;
    if (tid < JCH) {
        const int j = jb * JCH + tid;
        if (j < CLSH) {
            float s = 0.f;
#pragma unroll
            for (int ks = 0; ks < 8; ks++) s += part[tid][ks];
            v = tanhf(s * s_inv_sh + b3[j]) * W4[j];
        }
    }
    if (tid < 64) red[tid] = (tid < JCH) ? v : 0.f;
    __syncthreads();
    for (int st = 32; st > 0; st >>= 1) {
        if (tid < st) red[tid] += red[tid + st];
        __syncthreads();
    }
    if (tid == 0) g_sentp[b * JSPLIT + jb] = red[0];
}

// =====================================================================
// Kernel 4: finalize — sent sigmoid + all losses. 1 block, 64 threads.
// =====================================================================
__global__ void __launch_bounds__(64)
final_kernel(const float* __restrict__ b4,
             float* __restrict__ out,
             float* __restrict__ out_sent)
{
    const int b = threadIdx.x;

    float pre = b4[0];
#pragma unroll
    for (int jb = 0; jb < JSPLIT; jb++)
        pre += g_sentp[b * JSPLIT + jb];
    float sv = 1.f / (1.f + expf(-pre));
    out_sent[b] = sv;

    float maxm = -1e30f, minm = 1e30f, slab = -1e30f, tl = 0.f;
#pragma unroll
    for (int ss = 0; ss < PSPLIT; ss++) {
        int ci = b * PSPLIT + ss;
        maxm = fmaxf(maxm, g_cmax[ci]);
        minm = fminf(minm, g_cmin[ci]);
        slab = fmaxf(slab, g_cslab[ci]);
        tl  += g_ctl[ci];
    }

    float sl = sv - slab; sl *= sl;
    float ra = minm * minm;
    float d  = maxm - slab; float rb = d * d;

    __shared__ float s1[64], s2[64], s3[64], s4[64];
    s1[b] = sl; s2[b] = tl; s3[b] = ra; s4[b] = rb;
    __syncthreads();
    for (int st = 32; st > 0; st >>= 1) {
        if (b < st) { s1[b] += s1[b+st]; s2[b] += s2[b+st]; s3[b] += s3[b+st]; s4[b] += s4[b+st]; }
        __syncthreads();
    }
    if (b == 0) {
        float sentence = s1[0], token = s2[0], rega = s3[0], regb = s4[0];
        out[0] = sentence + token + 0.01f * (rega + regb);
        out[1] = sentence;
        out[2] = token;
        out[3] = rega;
        out[4] = regb;
    }
}

// =====================================================================
extern "C" void kernel_launch(void* const* d_in, const int* in_sizes, int n_in,
                              void* d_out, int out_size)
{
    const float* hs     = (const float*)d_in[0];
    const int*   off    = (const int*)  d_in[1];
    const float* labels = (const float*)d_in[2];
    const float* W1     = (const float*)d_in[3];
    const float* b1     = (const float*)d_in[4];
    const float* W2     = (const float*)d_in[5];
    const float* b2     = (const float*)d_in[6];
    const float* W3     = (const float*)d_in[7];
    const float* b3     = (const float*)d_in[8];
    const float* W4     = (const float*)d_in[9];
    const float* b4     = (const float*)d_in[10];

    float* out = (float*)d_out;
    float* out_hidden = out + OUT_HID_OFF;
    float* out_masked = out + OUT_MASK_OFF;
    float* out_sent   = out + OUT_SENT_OFF;

    float* tok; cudaGetSymbolAddress((void**)&tok, g_token_att);

    cudaFuncSetAttribute(att_gemm_kernel,
                         cudaFuncAttributeMaxDynamicSharedMemorySize,
                         ATT_SMEM_BYTES);

    // Stage A: token attention head (TF32 MMA, cp.async)
    att_gemm_kernel<<<NTOK / MT, 256, ATT_SMEM_BYTES>>>(hs, W1, b1, W2, b2, tok);

    // Stage B: fused segment-mask + pooling partials + hidden echo
    dim3 pg(BATCH, PSPLIT);
    pool_kernel<<<pg, 192>>>(hs, off, labels, tok, out_masked, out_hidden);

    // Stage C: sentence head j-split (scalar partials; comb eliminated)
    dim3 sg(BATCH, JSPLIT);
    sent_part_kernel<<<sg, 320>>>(W3, b3, W4);

    // Stage D: finalize sent + losses
    final_kernel<<<1, 64>>>(b4, out, out_sent);
}